// round 1
// baseline (speedup 1.0000x reference)
#include <cuda_runtime.h>
#include <cuda_bf16.h>
#include <math.h>

// Problem constants
#define SD 128      // STATE_DIM
#define NH 32       // HIDDEN
#define BATCH 512
#define WARPS_PER_BLOCK 4
#define THREADS (WARPS_PER_BLOCK * 32)

// Math identity used:
//   h is the same feature row for every node, and the GCN normalization sums
//   c[dst] = sum_{e: dst} deg[src]^-.5 deg[dst]^-.5 == 1 exactly for this graph.
//   => both convs are per-batch matvecs; the final feature-mean turns conv2
//   into a 32-dot with the row-means of W2.
//   out[b,n] = exp(log_amp[n,month]) * softplus( sum_h relu(feat[b]@W1 + b1)[h] * mean_n W2[h,n] + mean(b2) )

__global__ __launch_bounds__(THREADS) void gnm_kernel(
    const float* __restrict__ x,        // [512,128]
    const float* __restrict__ t,        // [1]
    const float* __restrict__ log_amp,  // [128,12]
    const float* __restrict__ W1,       // [129,32]
    const float* __restrict__ b1,       // [32]
    const float* __restrict__ W2,       // [32,128]
    const float* __restrict__ b2,       // [128]
    float* __restrict__ out)            // [512,128]
{
    __shared__ float s_amp[SD];
    __shared__ float s_w2m[NH];
    __shared__ float s_b2m;

    const float tv    = t[0];
    const int   month = (int)fmodf(tv, 12.0f);
    const float emb   = sinf(6.283185307179586f * tv * (1.0f / 12.0f));

    const int tid  = threadIdx.x;
    const int lane = tid & 31;
    const int warp = tid >> 5;

    // Per-block precompute (tiny; weights sit in L2 after first block)
    if (tid < SD) s_amp[tid] = expf(log_amp[tid * 12 + month]);
    if (tid < NH) {
        float s = 0.0f;
        #pragma unroll 16
        for (int n = 0; n < SD; n++) s += W2[tid * SD + n];
        s_w2m[tid] = s * (1.0f / SD);
    }
    if (warp == 1) {
        float s = b2[lane] + b2[lane + 32] + b2[lane + 64] + b2[lane + 96];
        #pragma unroll
        for (int off = 16; off; off >>= 1)
            s += __shfl_xor_sync(0xffffffffu, s, off);
        if (lane == 0) s_b2m = s * (1.0f / SD);
    }
    __syncthreads();

    // One warp per batch row; lane = hidden unit h
    const int b = blockIdx.x * WARPS_PER_BLOCK + warp;
    const float* __restrict__ xr = x + b * SD;

    float a0 = 0.f, a1 = 0.f, a2 = 0.f, a3 = 0.f;
    #pragma unroll
    for (int i = 0; i < SD; i += 4) {
        // all lanes read the same x addresses (L1 broadcast); W1 row reads are coalesced
        float4 xv = *reinterpret_cast<const float4*>(xr + i);
        a0 = fmaf(xv.x, W1[(i + 0) * NH + lane], a0);
        a1 = fmaf(xv.y, W1[(i + 1) * NH + lane], a1);
        a2 = fmaf(xv.z, W1[(i + 2) * NH + lane], a2);
        a3 = fmaf(xv.w, W1[(i + 3) * NH + lane], a3);
    }
    float v = (a0 + a1) + (a2 + a3);
    v += emb * W1[SD * NH + lane];   // contribution of the seasonal-embedding feature
    v += b1[lane];

    float r = fmaxf(v, 0.0f) * s_w2m[lane];
    #pragma unroll
    for (int off = 16; off; off >>= 1)
        r += __shfl_xor_sync(0xffffffffu, r, off);

    const float m  = r + s_b2m;
    // numerically-stable softplus matching jax.nn.softplus
    const float sp = (m > 0.0f) ? (m + log1pf(expf(-m))) : log1pf(expf(m));

    float* __restrict__ o = out + b * SD;
    #pragma unroll
    for (int n = lane; n < SD; n += 32)
        o[n] = s_amp[n] * sp;
}

extern "C" void kernel_launch(void* const* d_in, const int* in_sizes, int n_in,
                              void* d_out, int out_size)
{
    const float* x       = (const float*)d_in[0];
    const float* t       = (const float*)d_in[1];
    const float* log_amp = (const float*)d_in[2];
    const float* W1      = (const float*)d_in[3];
    const float* b1      = (const float*)d_in[4];
    const float* W2      = (const float*)d_in[5];
    const float* b2      = (const float*)d_in[6];
    float* out           = (float*)d_out;

    gnm_kernel<<<BATCH / WARPS_PER_BLOCK, THREADS>>>(x, t, log_amp, W1, b1, W2, b2, out);
}

// round 2
// speedup vs baseline: 1.1910x; 1.1910x over previous
#include <cuda_runtime.h>
#include <cuda_bf16.h>
#include <math.h>

// Problem constants
#define SD 128      // STATE_DIM
#define NH 32       // HIDDEN
#define BATCH 512
#define ROWS 4      // batch rows per block (one per warp)
#define THREADS 128

// Math identity (verified R1, rel_err 9e-8):
//   Every node sees the same feature row and the GCN normalization sums to 1
//   exactly for this graph, so both convs are per-batch matvecs and the
//   feature-mean collapses conv2 to a 32-dot with row-means of W2:
//   out[b,n] = exp(log_amp[n,month]) *
//              softplus( sum_h relu(x[b]@W1 + emb*W1[128,:] + b1)[h] * mean_n W2[h,n] + mean(b2) )

__global__ __launch_bounds__(THREADS) void gnm_kernel(
    const float* __restrict__ x,        // [512,128]
    const float* __restrict__ t,        // [1]
    const float* __restrict__ log_amp,  // [128,12]
    const float* __restrict__ W1,       // [129,32]
    const float* __restrict__ b1,       // [32]
    const float* __restrict__ W2,       // [32,128]
    const float* __restrict__ b2,       // [128]
    float* __restrict__ out)            // [512,128]
{
    __shared__ float s_x[ROWS * SD];
    __shared__ float s_amp[SD];
    __shared__ float s_w2m[NH];
    __shared__ float s_b2m;

    const int tid  = threadIdx.x;
    const int lane = tid & 31;
    const int warp = tid >> 5;
    const int b0   = blockIdx.x * ROWS;

    // ---------- phase 0: issue ALL independent global loads up front ----------
    // x: one coalesced float4 per thread covers the block's 4 rows
    const float4 xv = reinterpret_cast<const float4*>(x + b0 * SD)[tid];

    const float tv = t[0];

    // log_amp: full 12-month row per thread (independent of t -> no serial chain)
    // tid*12 floats = tid*48 bytes, always 16B-aligned
    const float4* lar = reinterpret_cast<const float4*>(log_amp + tid * 12);
    const float4 la0 = lar[0], la1 = lar[1], la2 = lar[2];

    // W2 row-sums: 4 threads per hidden row, 8 float4 each (shallow + vectorized)
    const int h = tid >> 2, q = tid & 3;
    const float4* w2r = reinterpret_cast<const float4*>(W2 + h * SD + q * 32);
    float w2s = 0.0f;
    #pragma unroll
    for (int i = 0; i < 8; i++) {
        const float4 v = w2r[i];
        w2s += (v.x + v.y) + (v.z + v.w);
    }

    float b2s = 0.0f;
    if (warp == 0) {
        const float4 bv = reinterpret_cast<const float4*>(b2)[lane];
        b2s = (bv.x + bv.y) + (bv.z + bv.w);
    }

    const float b1v = b1[lane];
    const float w1e = W1[SD * NH + lane];   // seasonal-embedding row of W1

    // ---------- phase 0b: local compute on landed data ----------
    reinterpret_cast<float4*>(s_x)[tid] = xv;

    const int month = (int)fmodf(tv, 12.0f);
    float la = la0.x;
    la = (month ==  1) ? la0.y : la;
    la = (month ==  2) ? la0.z : la;
    la = (month ==  3) ? la0.w : la;
    la = (month ==  4) ? la1.x : la;
    la = (month ==  5) ? la1.y : la;
    la = (month ==  6) ? la1.z : la;
    la = (month ==  7) ? la1.w : la;
    la = (month ==  8) ? la2.x : la;
    la = (month ==  9) ? la2.y : la;
    la = (month == 10) ? la2.z : la;
    la = (month == 11) ? la2.w : la;
    s_amp[tid] = expf(la);

    // quad-reduce the W2 partial sums (lanes q=0..3 of each row are adjacent)
    w2s += __shfl_xor_sync(0xffffffffu, w2s, 1);
    w2s += __shfl_xor_sync(0xffffffffu, w2s, 2);
    if (q == 0) s_w2m[h] = w2s * (1.0f / SD);

    if (warp == 0) {
        #pragma unroll
        for (int off = 16; off; off >>= 1)
            b2s += __shfl_xor_sync(0xffffffffu, b2s, off);
        if (lane == 0) s_b2m = b2s * (1.0f / SD);
    }

    const float emb = sinf(6.283185307179586f * tv * (1.0f / 12.0f));

    __syncthreads();

    // ---------- phase 1: matvec (warp = batch row, lane = hidden unit) ----------
    const float* __restrict__ xs = s_x + warp * SD;
    float a0 = 0.f, a1 = 0.f, a2 = 0.f, a3 = 0.f;
    #pragma unroll
    for (int i = 0; i < SD; i += 4) {
        // xs[*]: LDS broadcast; W1 reads coalesced per warp, shared across warps via L1
        a0 = fmaf(xs[i + 0], W1[(i + 0) * NH + lane], a0);
        a1 = fmaf(xs[i + 1], W1[(i + 1) * NH + lane], a1);
        a2 = fmaf(xs[i + 2], W1[(i + 2) * NH + lane], a2);
        a3 = fmaf(xs[i + 3], W1[(i + 3) * NH + lane], a3);
    }
    float v = (a0 + a1) + (a2 + a3) + fmaf(emb, w1e, b1v);

    float r = fmaxf(v, 0.0f) * s_w2m[lane];
    #pragma unroll
    for (int off = 16; off; off >>= 1)
        r += __shfl_xor_sync(0xffffffffu, r, off);

    const float m  = r + s_b2m;
    const float sp = fmaxf(m, 0.0f) + log1pf(expf(-fabsf(m)));  // stable softplus

    // vectorized epilogue: one STG.128 per lane
    const float4 av = reinterpret_cast<const float4*>(s_amp)[lane];
    float4 o;
    o.x = av.x * sp; o.y = av.y * sp; o.z = av.z * sp; o.w = av.w * sp;
    reinterpret_cast<float4*>(out + (b0 + warp) * SD)[lane] = o;
}

extern "C" void kernel_launch(void* const* d_in, const int* in_sizes, int n_in,
                              void* d_out, int out_size)
{
    const float* x       = (const float*)d_in[0];
    const float* t       = (const float*)d_in[1];
    const float* log_amp = (const float*)d_in[2];
    const float* W1      = (const float*)d_in[3];
    const float* b1      = (const float*)d_in[4];
    const float* W2      = (const float*)d_in[5];
    const float* b2      = (const float*)d_in[6];
    float* out           = (float*)d_out;

    gnm_kernel<<<BATCH / ROWS, THREADS>>>(x, t, log_amp, W1, b1, W2, b2, out);
}

// round 3
// speedup vs baseline: 1.4301x; 1.2007x over previous
#include <cuda_runtime.h>
#include <cuda_bf16.h>
#include <math.h>

// Problem constants
#define SD 128      // STATE_DIM
#define NH 32       // HIDDEN
#define BATCH 512
#define ROWS 4      // batch rows per block
#define THREADS 512 // (row 2b | chunk 2b | h 5b)

// Math identity (verified R1/R2, rel_err ~9e-8):
//   out[b,n] = exp(log_amp[n,month]) *
//     softplus( sum_h relu(x[b]@W1 + emb*W1[128,:] + b1)[h] * mean_n W2[h,n] + mean(b2) )

__global__ __launch_bounds__(THREADS) void gnm_kernel(
    const float* __restrict__ x,        // [512,128]
    const float* __restrict__ t,        // [1]
    const float* __restrict__ log_amp,  // [128,12]
    const float* __restrict__ W1,       // [129,32]
    const float* __restrict__ b1,       // [32]
    const float* __restrict__ W2,       // [32,128]
    const float* __restrict__ b2,       // [128]
    float* __restrict__ out)            // [512,128]
{
    __shared__ float s_part[ROWS * 4 * NH];  // [row][chunk][h]
    __shared__ float s_w2p[4 * NH];          // W2 row-sum partials [chunk][h]
    __shared__ float s_amp[SD];
    __shared__ float s_b2m;

    const int tid   = threadIdx.x;
    const int h     = tid & 31;          // hidden unit (lane)
    const int chunk = (tid >> 5) & 3;    // input chunk of 32
    const int row   = tid >> 7;          // batch row within block
    const int b0    = blockIdx.x * ROWS;

    // ---------------- phase 0: everything independent, one barrier ----------------
    const float tv = t[0];

    // x: one coalesced LDG per lane (warp owns 32 inputs of its row/chunk)
    const float xv = x[(b0 + row) * SD + chunk * 32 + h];

    // W1 slice for this thread's (chunk, h): 32 values, coalesced across lanes
    const float* __restrict__ w1p = W1 + (chunk * 32) * NH + h;

    // matvec partial via warp shuffle broadcast of xv (no smem round-trip)
    float a0 = 0.f, a1 = 0.f, a2 = 0.f, a3 = 0.f;
    #pragma unroll
    for (int j = 0; j < 32; j += 4) {
        const float x0 = __shfl_sync(0xffffffffu, xv, j + 0);
        const float x1 = __shfl_sync(0xffffffffu, xv, j + 1);
        const float x2 = __shfl_sync(0xffffffffu, xv, j + 2);
        const float x3 = __shfl_sync(0xffffffffu, xv, j + 3);
        a0 = fmaf(x0, w1p[(j + 0) * NH], a0);
        a1 = fmaf(x1, w1p[(j + 1) * NH], a1);
        a2 = fmaf(x2, w1p[(j + 2) * NH], a2);
        a3 = fmaf(x3, w1p[(j + 3) * NH], a3);
    }
    s_part[tid & 511] = ((a0 + a1) + (a2 + a3));   // [row][chunk][h] == tid layout

    // W2 row-sum partials: rows 0 threads (tid<128) redundant? spread: threads of row 0
    if (row == 0) {
        // thread (chunk,h): sum W2[h][chunk*32 .. +32)
        const float4* w2r = reinterpret_cast<const float4*>(W2 + h * SD + chunk * 32);
        float s = 0.f;
        #pragma unroll
        for (int i = 0; i < 8; i++) {
            const float4 v = w2r[i];
            s += (v.x + v.y) + (v.z + v.w);
        }
        s_w2p[chunk * NH + h] = s;
    }

    // amp table: threads 256..383 (row==2) handle n = chunk*32+h
    if (row == 2) {
        const int n = chunk * 32 + h;
        const float4* lar = reinterpret_cast<const float4*>(log_amp + n * 12);
        const float4 la0 = lar[0], la1 = lar[1], la2 = lar[2];
        const int month = (int)fmodf(tv, 12.0f);
        float la = la0.x;
        la = (month ==  1) ? la0.y : la;
        la = (month ==  2) ? la0.z : la;
        la = (month ==  3) ? la0.w : la;
        la = (month ==  4) ? la1.x : la;
        la = (month ==  5) ? la1.y : la;
        la = (month ==  6) ? la1.z : la;
        la = (month ==  7) ? la1.w : la;
        la = (month ==  8) ? la2.x : la;
        la = (month ==  9) ? la2.y : la;
        la = (month == 10) ? la2.z : la;
        la = (month == 11) ? la2.w : la;
        s_amp[n] = expf(la);
    }

    // b2 mean: warp 12 (row==3, chunk==0)
    if (row == 3 && chunk == 0) {
        const float4 bv = reinterpret_cast<const float4*>(b2)[h];
        float s = (bv.x + bv.y) + (bv.z + bv.w);
        #pragma unroll
        for (int off = 16; off; off >>= 1)
            s += __shfl_xor_sync(0xffffffffu, s, off);
        if (h == 0) s_b2m = s * (1.0f / SD);
    }

    __syncthreads();

    // ---------------- phase 1: warps 0-3 finish their row ----------------
    if (tid < ROWS * NH) {
        const int r = tid >> 5;          // row (= warp id here)
        // combine chunk partials for (r, h)
        const float* p = s_part + r * (4 * NH) + h;
        float v = ((p[0] + p[NH]) + (p[2 * NH] + p[3 * NH]));

        const float emb = sinf(6.283185307179586f * tv * (1.0f / 12.0f));
        v += fmaf(emb, W1[SD * NH + h], b1[h]);

        // w2 mean for h
        const float w2m = ((s_w2p[h] + s_w2p[NH + h]) +
                           (s_w2p[2 * NH + h] + s_w2p[3 * NH + h])) * (1.0f / SD);

        float rsum = fmaxf(v, 0.0f) * w2m;
        #pragma unroll
        for (int off = 16; off; off >>= 1)
            rsum += __shfl_xor_sync(0xffffffffu, rsum, off);

        const float m  = rsum + s_b2m;
        const float sp = fmaxf(m, 0.0f) + log1pf(expf(-fabsf(m)));  // stable softplus

        const float4 av = reinterpret_cast<const float4*>(s_amp)[h];
        float4 o;
        o.x = av.x * sp; o.y = av.y * sp; o.z = av.z * sp; o.w = av.w * sp;
        reinterpret_cast<float4*>(out + (b0 + r) * SD)[h] = o;
    }
}

extern "C" void kernel_launch(void* const* d_in, const int* in_sizes, int n_in,
                              void* d_out, int out_size)
{
    const float* x       = (const float*)d_in[0];
    const float* t       = (const float*)d_in[1];
    const float* log_amp = (const float*)d_in[2];
    const float* W1      = (const float*)d_in[3];
    const float* b1      = (const float*)d_in[4];
    const float* W2      = (const float*)d_in[5];
    const float* b2      = (const float*)d_in[6];
    float* out           = (float*)d_out;

    gnm_kernel<<<BATCH / ROWS, THREADS>>>(x, t, log_amp, W1, b1, W2, b2, out);
}

// round 4
// speedup vs baseline: 1.9275x; 1.3478x over previous
#include <cuda_runtime.h>
#include <cuda_bf16.h>
#include <math.h>

// Problem constants
#define SD 128      // STATE_DIM
#define NH 32       // HIDDEN
#define BATCH 512
#define ROWS 4      // batch rows per block
#define THREADS 512 // (row 2b | chunk 2b | h 5b)

// Math identity (verified R1-R3, rel_err ~9e-8):
//   out[b,n] = exp(log_amp[n,month]) *
//     softplus( sum_h relu(x[b]@W1 + emb*W1[128,:] + b1)[h] * mean_n W2[h,n] + mean(b2) )

__global__ __launch_bounds__(THREADS) void gnm_kernel(
    const float* __restrict__ x,        // [512,128]
    const float* __restrict__ t,        // [1]
    const float* __restrict__ log_amp,  // [128,12]
    const float* __restrict__ W1,       // [129,32]
    const float* __restrict__ b1,       // [32]
    const float* __restrict__ W2,       // [32,128]
    const float* __restrict__ b2,       // [128]
    float* __restrict__ out)            // [512,128]
{
    __shared__ float s_part[ROWS * 4 * NH];  // [row][chunk][h]
    __shared__ float s_w2m[NH];              // W2 row means
    __shared__ float s_amp[SD];
    __shared__ float s_b2m;

    const int tid   = threadIdx.x;
    const int h     = tid & 31;          // lane
    const int chunk = (tid >> 5) & 3;    // input chunk of 32
    const int row   = tid >> 7;          // batch row within block
    const int b0    = blockIdx.x * ROWS;

    // ---------------- phase 0: everything independent, one barrier ----------------
    const float tv = t[0];

    // matvec partial for (row, chunk, h): coalesced x load + shfl broadcast
    const float xv = x[(b0 + row) * SD + chunk * 32 + h];
    const float* __restrict__ w1p = W1 + (chunk * 32) * NH + h;

    float a0 = 0.f, a1 = 0.f, a2 = 0.f, a3 = 0.f;
    #pragma unroll
    for (int j = 0; j < 32; j += 4) {
        const float x0 = __shfl_sync(0xffffffffu, xv, j + 0);
        const float x1 = __shfl_sync(0xffffffffu, xv, j + 1);
        const float x2 = __shfl_sync(0xffffffffu, xv, j + 2);
        const float x3 = __shfl_sync(0xffffffffu, xv, j + 3);
        a0 = fmaf(x0, w1p[(j + 0) * NH], a0);
        a1 = fmaf(x1, w1p[(j + 1) * NH], a1);
        a2 = fmaf(x2, w1p[(j + 2) * NH], a2);
        a3 = fmaf(x3, w1p[(j + 3) * NH], a3);
    }
    s_part[tid & 511] = ((a0 + a1) + (a2 + a3));

    // ---- aux work, partitioned by row group ----
    if ((row & 1) == 0) {
        // rows 0 and 2: coalesced W2 row-means. 8 warps, 4 W2 rows each.
        // warp g in 0..7; iteration i covers W2 row (i*8+g), read as 32 coalesced float4.
        const int g = (row == 0) ? chunk : (4 + chunk);
        const float4* __restrict__ w2f4 = reinterpret_cast<const float4*>(W2);
        #pragma unroll
        for (int i = 0; i < 4; i++) {
            const float4 v = w2f4[i * 256 + g * 32 + h];   // row = i*8+g, coalesced
            float s = (v.x + v.y) + (v.z + v.w);
            #pragma unroll
            for (int off = 16; off; off >>= 1)
                s += __shfl_xor_sync(0xffffffffu, s, off);
            if (h == 0) s_w2m[i * 8 + g] = s * (1.0f / SD);
        }
    } else if (row == 1) {
        // amp table: thread n = tid-128 in 0..127
        const int n = tid & 127;
        const float4* lar = reinterpret_cast<const float4*>(log_amp + n * 12);
        const float4 la0 = lar[0], la1 = lar[1], la2 = lar[2];
        const float tm = (tv >= 12.0f) ? (tv - 12.0f) : tv;   // t in [0,24)
        const int month = (int)tm;
        float la = la0.x;
        la = (month ==  1) ? la0.y : la;
        la = (month ==  2) ? la0.z : la;
        la = (month ==  3) ? la0.w : la;
        la = (month ==  4) ? la1.x : la;
        la = (month ==  5) ? la1.y : la;
        la = (month ==  6) ? la1.z : la;
        la = (month ==  7) ? la1.w : la;
        la = (month ==  8) ? la2.x : la;
        la = (month ==  9) ? la2.y : la;
        la = (month == 10) ? la2.z : la;
        la = (month == 11) ? la2.w : la;
        s_amp[n] = __expf(la);
    }

    // row 3: phase-1 owners. Prefetch everything phase 1 needs BEFORE the barrier.
    float b1v = 0.f, w1e = 0.f, emb = 0.f;
    if (row == 3) {
        b1v = b1[h];
        w1e = W1[SD * NH + h];
        emb = __sinf(0.5235987755982988f * tv);   // 2*pi/12 * t
        if (chunk == 1) {
            // b2 mean (one warp)
            const float4 bv = reinterpret_cast<const float4*>(b2)[h];
            float s = (bv.x + bv.y) + (bv.z + bv.w);
            #pragma unroll
            for (int off = 16; off; off >>= 1)
                s += __shfl_xor_sync(0xffffffffu, s, off);
            if (h == 0) s_b2m = s * (1.0f / SD);
        }
    }

    __syncthreads();

    // ---------------- phase 1: row-3 warps finish (warp chunk == batch row r) ----------------
    if (row == 3) {
        const int r = chunk;
        const float* p = s_part + r * (4 * NH) + h;
        float v = ((p[0] + p[NH]) + (p[2 * NH] + p[3 * NH]));
        v += fmaf(emb, w1e, b1v);

        float rsum = fmaxf(v, 0.0f) * s_w2m[h];
        #pragma unroll
        for (int off = 16; off; off >>= 1)
            rsum += __shfl_xor_sync(0xffffffffu, rsum, off);

        const float m  = rsum + s_b2m;
        const float sp = fmaxf(m, 0.0f) + log1pf(__expf(-fabsf(m)));  // stable softplus

        const float4 av = reinterpret_cast<const float4*>(s_amp)[h];
        float4 o;
        o.x = av.x * sp; o.y = av.y * sp; o.z = av.z * sp; o.w = av.w * sp;
        reinterpret_cast<float4*>(out + (b0 + r) * SD)[h] = o;
    }
}

extern "C" void kernel_launch(void* const* d_in, const int* in_sizes, int n_in,
                              void* d_out, int out_size)
{
    const float* x       = (const float*)d_in[0];
    const float* t       = (const float*)d_in[1];
    const float* log_amp = (const float*)d_in[2];
    const float* W1      = (const float*)d_in[3];
    const float* b1      = (const float*)d_in[4];
    const float* W2      = (const float*)d_in[5];
    const float* b2      = (const float*)d_in[6];
    float* out           = (float*)d_out;

    gnm_kernel<<<BATCH / ROWS, THREADS>>>(x, t, log_amp, W1, b1, W2, b2, out);
}